// round 3
// baseline (speedup 1.0000x reference)
#include <cuda_runtime.h>

#define B_DIM 1024
#define T_DIM 256
#define D_DIM 64
#define H_DIM 128
#define GH 256          // 2H
#define XCOLS 384       // 256 gate cols + 128 cand cols
#define RROWS 4
#define NGROUPS (B_DIM / RROWS)   // 256
#define KPAD 132        // padded k-stride (floats), conflict-free for stride-KPAD LDS.128

// Scratch (device globals: no allocation allowed).
static __device__ float g_Xbuf[(size_t)B_DIM * T_DIM * XCOLS]; // ~402 MB
static __device__ int   g_perm[B_DIM];
static __device__ int   g_counter;

typedef unsigned long long ull;

__device__ __forceinline__ float fast_sigmoid(float z) {
    return __fdividef(1.0f, 1.0f + __expf(-z));
}
__device__ __forceinline__ float fast_tanh(float z) {
    return 1.0f - __fdividef(2.0f, __expf(2.0f * z) + 1.0f);
}

// packed fp32x2 helpers (Blackwell FFMA2 — PTX-only, exact fp32)
__device__ __forceinline__ void ffma2(ull& acc, ull a, ull b) {
    asm("fma.rn.f32x2 %0, %1, %2, %0;" : "+l"(acc) : "l"(a), "l"(b));
}
__device__ __forceinline__ ull pack2(float lo, float hi) {
    ull r;
    asm("mov.b64 %0, {%1, %2};" : "=l"(r) : "f"(lo), "f"(hi));
    return r;
}
__device__ __forceinline__ ull splat2(float v) {
    ull r;
    asm("mov.b64 %0, {%1, %1};" : "=l"(r) : "f"(v));
    return r;
}
__device__ __forceinline__ float hsum2(ull p) {
    float lo, hi;
    asm("mov.b64 {%0, %1}, %2;" : "=f"(lo), "=f"(hi) : "l"(p));
    return lo + hi;
}
__device__ __forceinline__ ull fadd2(ull a, ull b) {
    ull r;
    asm("add.rn.f32x2 %0, %1, %2;" : "=l"(r) : "l"(a), "l"(b));
    return r;
}

// ---------------------------------------------------------------------------
// K0: counting sort rows by seq_len (descending, LPT) + reset work counter.
// ---------------------------------------------------------------------------
__global__ void sort_kernel(const int* __restrict__ seq_lens) {
    __shared__ int hist[256];
    __shared__ int offs[256];
    int tid = threadIdx.x;
    hist[tid] = 0;
    __syncthreads();
    for (int r = tid; r < B_DIM; r += 256) {
        int L = seq_lens[r];
        L = min(max(L, 0), 255);
        atomicAdd(&hist[L], 1);
    }
    __syncthreads();
    if (tid == 0) {
        int run = 0;
        for (int k = 255; k >= 0; k--) { offs[k] = run; run += hist[k]; }
        g_counter = 0;
    }
    __syncthreads();
    for (int r = tid; r < B_DIM; r += 256) {
        int L = seq_lens[r];
        L = min(max(L, 0), 255);
        int pos = atomicAdd(&offs[L], 1);
        g_perm[pos] = r;
    }
}

// ---------------------------------------------------------------------------
// K1: projection (FFMA2).  Xbuf[b,t,0:256] = emb @ Wg_x + gb,
//                          Xbuf[b,t,256:384] = emb @ Wc_x + cb.
// 512 threads, tile = 64 t-rows x 384 cols.
// Thread micro-tile: 4 rows (tr+16ri) x 6 column-PAIRS (2tc+64ci).
// ---------------------------------------------------------------------------
__global__ void __launch_bounds__(512) proj_kernel(
    const int* __restrict__ item_his,
    const int* __restrict__ seq_lens,
    const float* __restrict__ embedding,
    const float* __restrict__ gate_kernel,
    const float* __restrict__ gate_bias,
    const float* __restrict__ cand_kernel,
    const float* __restrict__ cand_bias)
{
    extern __shared__ float sm[];
    float* Wx = sm;                    // [64][384]
    float* xs = Wx + 64 * XCOLS;       // [64][64]
    float* bs = xs + 64 * 64;          // [384]
    __shared__ int items_s[64];

    int b  = blockIdx.y;
    int t0 = blockIdx.x * 64;
    int len = seq_lens[b];
    if (t0 >= len) return;
    int tid = threadIdx.x;

    for (int idx = tid; idx < 64 * GH; idx += 512) {
        int k = idx >> 8, c = idx & 255;
        Wx[k * XCOLS + c] = gate_kernel[k * GH + c];
    }
    for (int idx = tid; idx < 64 * H_DIM; idx += 512) {
        int k = idx >> 7, c = idx & 127;
        Wx[k * XCOLS + 256 + c] = cand_kernel[k * H_DIM + c];
    }
    if (tid < 256) bs[tid] = gate_bias[tid];
    else if (tid < 384) bs[tid] = cand_bias[tid - 256];
    if (tid < 64) items_s[tid] = item_his[b * T_DIM + t0 + tid];
    __syncthreads();

    for (int e = tid; e < 64 * 64; e += 512) {
        int rr = e >> 6, k = e & 63;
        xs[e] = embedding[items_s[rr] * 64 + k];
    }
    __syncthreads();

    int tc = tid & 31;     // column pair base = 2*tc
    int tr = tid >> 5;     // row base (0..15), rows tr + 16*ri
    ull acc[4][6];
    #pragma unroll
    for (int ri = 0; ri < 4; ri++)
        #pragma unroll
        for (int ci = 0; ci < 6; ci++) acc[ri][ci] = 0ULL;

    #pragma unroll 4
    for (int k = 0; k < 64; k++) {
        ull A0 = splat2(xs[(tr + 0)  * 64 + k]);
        ull A1 = splat2(xs[(tr + 16) * 64 + k]);
        ull A2 = splat2(xs[(tr + 32) * 64 + k]);
        ull A3 = splat2(xs[(tr + 48) * 64 + k]);
        const float* wrow = Wx + k * XCOLS + 2 * tc;
        #pragma unroll
        for (int ci = 0; ci < 6; ci++) {
            ull w = *(const ull*)(wrow + 64 * ci);
            ffma2(acc[0][ci], A0, w);
            ffma2(acc[1][ci], A1, w);
            ffma2(acc[2][ci], A2, w);
            ffma2(acc[3][ci], A3, w);
        }
    }

    #pragma unroll
    for (int ri = 0; ri < 4; ri++) {
        int t = t0 + tr + 16 * ri;
        float* dst = g_Xbuf + (size_t)(b * T_DIM + t) * XCOLS;
        #pragma unroll
        for (int ci = 0; ci < 6; ci++) {
            int c = 2 * tc + 64 * ci;
            ull bias2 = *(const ull*)(bs + c);
            *(ull*)(dst + c) = fadd2(acc[ri][ci], bias2);
        }
    }
}

// ---------------------------------------------------------------------------
// K2: persistent GRU recurrence, 512 threads/CTA, 4 rows/group.
// Gate stage: thread (j = tid&255, p = tid>>8) -> gate col j for rows 2p,2p+1
//             (full k=128 dot, no partial exchange).
// Cand stage: thread (i = tid&127, r = tid>>7) -> cand col i for row r.
// 2 barriers per step, no partial combines.
// ---------------------------------------------------------------------------
__global__ void __launch_bounds__(512, 1) gru_kernel(
    const int* __restrict__ seq_lens,
    const float* __restrict__ gate_kernel,
    const float* __restrict__ cand_kernel,
    float* __restrict__ out)
{
    extern __shared__ float sm[];
    float* Ug   = sm;                          // [256][KPAD]  Ug[j][k] = W_g[64+k][j]
    float* Uc   = Ug + GH * KPAD;              // [128][KPAD]  Uc[i][k] = W_c[64+k][i]
    float* h_s  = Uc + H_DIM * KPAD;           // [4][128]
    float* rh_s = h_s + RROWS * H_DIM;         // [4][128]
    float* u_s  = rh_s + RROWS * H_DIM;        // [4][128]
    __shared__ int s_g;
    __shared__ int s_b[RROWS];
    __shared__ int s_len[RROWS];

    int tid = threadIdx.x;

    // stage transposed recurrent weights (once per block)
    for (int idx = tid; idx < H_DIM * GH; idx += 512) {
        int k = idx >> 8, j = idx & 255;
        Ug[j * KPAD + k] = gate_kernel[(D_DIM + k) * GH + j];
    }
    for (int idx = tid; idx < H_DIM * H_DIM; idx += 512) {
        int k = idx >> 7, i = idx & 127;
        Uc[i * KPAD + k] = cand_kernel[(D_DIM + k) * H_DIM + i];
    }

    int j = tid & 255;          // gate column
    int p = tid >> 8;           // gate row-pair (rows 2p, 2p+1)
    int i = tid & 127;          // cand column
    int r = tid >> 7;           // cand row (0..3)

    const ulonglong2* Ug2 = (const ulonglong2*)(Ug + j * KPAD);
    const ulonglong2* Uc2 = (const ulonglong2*)(Uc + i * KPAD);
    const ulonglong2* hA2 = (const ulonglong2*)(h_s + (2 * p) * H_DIM);
    const ulonglong2* hB2 = (const ulonglong2*)(h_s + (2 * p + 1) * H_DIM);
    const ulonglong2* rh2 = (const ulonglong2*)(rh_s + r * H_DIM);
    float* hgA = h_s + (2 * p) * H_DIM;        // gate-stage h rows
    float* hgB = h_s + (2 * p + 1) * H_DIM;
    __syncthreads();

    while (true) {
        if (tid == 0) s_g = atomicAdd(&g_counter, 1);
        __syncthreads();
        int g = s_g;
        if (g >= NGROUPS) break;

        if (tid < RROWS) {
            int row = g_perm[g * RROWS + tid];
            s_b[tid]   = row;
            s_len[tid] = min(max(seq_lens[row], 0), T_DIM);
        }
        for (int e = tid; e < RROWS * H_DIM; e += 512) h_s[e] = 0.0f;
        __syncthreads();

        int L = max(max(s_len[0], s_len[1]), max(s_len[2], s_len[3]));
        int lenR = s_len[r];

        const float* xgA = g_Xbuf + s_b[2 * p]     * (T_DIM * XCOLS) + j;
        const float* xgB = g_Xbuf + s_b[2 * p + 1] * (T_DIM * XCOLS) + j;
        const float* xc  = g_Xbuf + s_b[r]         * (T_DIM * XCOLS) + 256 + i;

        for (int t = 0; t < L; t++) {
            // early global loads (consumed after the k-loops)
            float vgA = xgA[t * XCOLS];
            float vgB = xgB[t * XCOLS];
            float vc  = xc[t * XCOLS];

            // gate dot: col j, rows 2p / 2p+1, full k=128
            ull a0 = pack2(vgA, 0.0f);
            ull a1 = pack2(vgB, 0.0f);
            #pragma unroll 8
            for (int k4 = 0; k4 < H_DIM / 4; k4++) {
                ulonglong2 w  = Ug2[k4];
                ulonglong2 va = hA2[k4];
                ffma2(a0, va.x, w.x); ffma2(a0, va.y, w.y);
                ulonglong2 vb = hB2[k4];
                ffma2(a1, vb.x, w.x); ffma2(a1, vb.y, w.y);
            }
            float s0 = fast_sigmoid(hsum2(a0));
            float s1 = fast_sigmoid(hsum2(a1));

            if (j < H_DIM) {          // r-gate
                rh_s[(2 * p) * H_DIM + j]     = s0 * hgA[j];
                rh_s[(2 * p + 1) * H_DIM + j] = s1 * hgB[j];
            } else {                  // u-gate
                u_s[(2 * p) * H_DIM + (j - H_DIM)]     = s0;
                u_s[(2 * p + 1) * H_DIM + (j - H_DIM)] = s1;
            }
            __syncthreads();

            // cand dot: col i, row r, full k=128
            ull c0 = pack2(vc, 0.0f);
            #pragma unroll 8
            for (int k4 = 0; k4 < H_DIM / 4; k4++) {
                ulonglong2 w = Uc2[k4];
                ulonglong2 v = rh2[k4];
                ffma2(c0, v.x, w.x); ffma2(c0, v.y, w.y);
            }
            float c  = fast_tanh(hsum2(c0));
            float u  = u_s[r * H_DIM + i];
            float hv = h_s[r * H_DIM + i];
            float hn = fmaf(u, hv - c, c);      // u*h + (1-u)*c
            if (t < lenR) h_s[r * H_DIM + i] = hn;
            __syncthreads();
        }

        out[s_b[r] * H_DIM + i] = h_s[r * H_DIM + i];
        __syncthreads();
    }
}

// ---------------------------------------------------------------------------
extern "C" void kernel_launch(void* const* d_in, const int* in_sizes, int n_in,
                              void* d_out, int out_size) {
    (void)in_sizes; (void)n_in; (void)out_size;
    const int*   item_his    = (const int*)  d_in[0];
    const int*   seq_lens    = (const int*)  d_in[1];
    const float* embedding   = (const float*)d_in[2];
    const float* gate_kernel = (const float*)d_in[3];
    const float* gate_bias   = (const float*)d_in[4];
    const float* cand_kernel = (const float*)d_in[5];
    const float* cand_bias   = (const float*)d_in[6];
    float*       out         = (float*)d_out;

    const int smem_proj = (64 * XCOLS + 64 * 64 + XCOLS) * 4;                 // 116 KB
    const int smem_gru  = (GH * KPAD + H_DIM * KPAD + 3 * RROWS * H_DIM) * 4; // ~209 KB
    cudaFuncSetAttribute(proj_kernel, cudaFuncAttributeMaxDynamicSharedMemorySize, smem_proj);
    cudaFuncSetAttribute(gru_kernel,  cudaFuncAttributeMaxDynamicSharedMemorySize, smem_gru);

    sort_kernel<<<1, 256>>>(seq_lens);
    proj_kernel<<<dim3(T_DIM / 64, B_DIM), 512, smem_proj>>>(
        item_his, seq_lens, embedding, gate_kernel, gate_bias, cand_kernel, cand_bias);
    gru_kernel<<<148, 512, smem_gru>>>(seq_lens, gate_kernel, cand_kernel, out);
}